// round 6
// baseline (speedup 1.0000x reference)
#include <cuda_runtime.h>

#define DD 256      // feature/hidden dim
#define GD 768      // 3*DD gate dim
#define LL 96       // max group length
#define TG 14       // groups per block
#define BMAX 2048
#define NT 512      // threads per block (2 warpgroups: ih / hh)

typedef unsigned long long u64;

// ---------------- device scratch ----------------
__device__ int    g_order[BMAX * LL];          // edge id per (group, t), -1 = pad
__device__ int    g_cnt[BMAX];                 // group sizes
__device__ float4 g_wpack[4 * 64 * GD];        // [mat][kb][gd] -> W[gd][4kb..4kb+3]
__device__ float  g_u0[(LL + 1) * DD];         // universal pad trajectory: h0 after s steps
__device__ float  g_u1[(LL + 1) * DD];         // h1 after s steps
__device__ float  g_ua[(LL + 1) * DD];         // sum of h1 over first s steps

// ---------------- helpers ----------------
__device__ __forceinline__ u64 fma2(u64 a, u64 b, u64 c) {
    u64 d;
    asm("fma.rn.f32x2 %0, %1, %2, %3;" : "=l"(d) : "l"(a), "l"(b), "l"(c));
    return d;
}
__device__ __forceinline__ float red2(u64 a) {
    float lo = __uint_as_float((unsigned)(a & 0xffffffffULL));
    float hi = __uint_as_float((unsigned)(a >> 32));
    return lo + hi;
}
__device__ __forceinline__ u64 set_lo(float v) { return (u64)__float_as_uint(v); }

__device__ __forceinline__ float sigmoidf_(float v) {
    return __fdividef(1.f, 1.f + __expf(-v));
}
__device__ __forceinline__ float tanhf_(float v) {
    float t = __expf(2.f * v);
    return 1.f - __fdividef(2.f, t + 1.f);
}

// ---------------- fused setup: per-group timestamp sort + weight pack ----------------
__global__ void setup_k(const float* __restrict__ ts, const int* __restrict__ index,
                        int E, int B,
                        const float* __restrict__ w0, const float* __restrict__ w1,
                        const float* __restrict__ w2, const float* __restrict__ w3)
{
    const int b = blockIdx.x;
    if (b < B) {
        __shared__ int   lbub[2];
        __shared__ float sts[LL];
        const int i = threadIdx.x;
        if (i < 2) {
            const int key = b + i;
            int lo = 0, hi = E;
            while (lo < hi) {
                int m = (lo + hi) >> 1;
                if (index[m] < key) lo = m + 1; else hi = m;
            }
            lbub[i] = lo;
        }
        __syncthreads();
        const int off = lbub[0];
        const int c   = lbub[1] - lbub[0];
        if (i == 0) g_cnt[b] = c;
        if (i < c)  sts[i] = ts[off + i];
        if (i < LL) g_order[b * LL + i] = -1;
        __syncthreads();
        if (i < c) {
            const float ti = sts[i];
            int rank = 0;
            for (int j = 0; j < c; ++j) {
                float tj = sts[j];
                rank += (tj < ti || (tj == ti && j < i)) ? 1 : 0;
            }
            g_order[b * LL + (LL - c + rank)] = off + i;
        }
    } else {
        int idx = (b - B) * 256 + threadIdx.x;
        if (idx < 4 * 64 * GD) {
            int m   = idx / (64 * GD);
            int rem = idx - m * 64 * GD;
            int kb  = rem / GD;
            int dd  = rem - kb * GD;
            const float* W = (m == 0) ? w0 : (m == 1) ? w1 : (m == 2) ? w2 : w3;
            const float* p = W + dd * DD + kb * 4;
            g_wpack[idx] = make_float4(p[0], p[1], p[2], p[3]);
        }
    }
}

// ---------------- universal pad trajectory (x = 0, h from 0), 1 block of 256 ----------------
__global__ void pad_k(const float* __restrict__ wih1, const float* __restrict__ whh0,
                      const float* __restrict__ whh1,
                      const float* __restrict__ bih0, const float* __restrict__ bhh0,
                      const float* __restrict__ bih1, const float* __restrict__ bhh1)
{
    __shared__ __align__(16) float h0[DD];
    __shared__ __align__(16) float h1[DD];
    const int d = threadIdx.x;
    h0[d] = 0.f; h1[d] = 0.f;
    float acc = 0.f;
    g_u0[d] = 0.f; g_u1[d] = 0.f; g_ua[d] = 0.f;

    const float b0r  = bih0[d] + bhh0[d];
    const float b0z  = bih0[DD + d] + bhh0[DD + d];
    const float b0xn = bih0[2 * DD + d];
    const float b0hn = bhh0[2 * DD + d];
    const float b1r  = bih1[d] + bhh1[d];
    const float b1z  = bih1[DD + d] + bhh1[DD + d];
    const float b1xn = bih1[2 * DD + d];
    const float b1hn = bhh1[2 * DD + d];

    const float* r0r = whh0 + (size_t)d * DD;
    const float* r0z = whh0 + (size_t)(DD + d) * DD;
    const float* r0n = whh0 + (size_t)(2 * DD + d) * DD;
    const float* x1r = wih1 + (size_t)d * DD;
    const float* x1z = wih1 + (size_t)(DD + d) * DD;
    const float* x1n = wih1 + (size_t)(2 * DD + d) * DD;
    const float* r1r = whh1 + (size_t)d * DD;
    const float* r1z = whh1 + (size_t)(DD + d) * DD;
    const float* r1n = whh1 + (size_t)(2 * DD + d) * DD;
    __syncthreads();

    for (int s = 1; s <= LL; ++s) {
        // layer 0: x = 0 -> input part is just bias
        u64 a0 = 0, a1 = 0, a2 = 0;
        for (int kb = 0; kb < 64; ++kb) {
            ulonglong2 hv = *(const ulonglong2*)(h0 + kb * 4);
            ulonglong2 wr = *(const ulonglong2*)(r0r + kb * 4);
            ulonglong2 wz = *(const ulonglong2*)(r0z + kb * 4);
            ulonglong2 wn = *(const ulonglong2*)(r0n + kb * 4);
            a0 = fma2(wr.x, hv.x, a0); a0 = fma2(wr.y, hv.y, a0);
            a1 = fma2(wz.x, hv.x, a1); a1 = fma2(wz.y, hv.y, a1);
            a2 = fma2(wn.x, hv.x, a2); a2 = fma2(wn.y, hv.y, a2);
        }
        float r   = sigmoidf_(b0r + red2(a0));
        float z   = sigmoidf_(b0z + red2(a1));
        float n   = tanhf_(b0xn + r * (b0hn + red2(a2)));
        float h0n = fmaf(z, h0[d] - n, n);
        __syncthreads();
        h0[d] = h0n;
        __syncthreads();

        // layer 1: input = new h0
        u64 c0 = 0, c1 = 0, c2 = 0, c3 = 0, c4 = 0, c5 = 0;
        for (int kb = 0; kb < 64; ++kb) {
            ulonglong2 xv = *(const ulonglong2*)(h0 + kb * 4);
            ulonglong2 hv = *(const ulonglong2*)(h1 + kb * 4);
            ulonglong2 wxr = *(const ulonglong2*)(x1r + kb * 4);
            ulonglong2 wxz = *(const ulonglong2*)(x1z + kb * 4);
            ulonglong2 wxn = *(const ulonglong2*)(x1n + kb * 4);
            ulonglong2 whr = *(const ulonglong2*)(r1r + kb * 4);
            ulonglong2 whz = *(const ulonglong2*)(r1z + kb * 4);
            ulonglong2 whn = *(const ulonglong2*)(r1n + kb * 4);
            c0 = fma2(wxr.x, xv.x, c0); c0 = fma2(wxr.y, xv.y, c0);
            c1 = fma2(wxz.x, xv.x, c1); c1 = fma2(wxz.y, xv.y, c1);
            c2 = fma2(wxn.x, xv.x, c2); c2 = fma2(wxn.y, xv.y, c2);
            c3 = fma2(whr.x, hv.x, c3); c3 = fma2(whr.y, hv.y, c3);
            c4 = fma2(whz.x, hv.x, c4); c4 = fma2(whz.y, hv.y, c4);
            c5 = fma2(whn.x, hv.x, c5); c5 = fma2(whn.y, hv.y, c5);
        }
        float r1  = sigmoidf_(b1r + red2(c0) + red2(c3));
        float z1  = sigmoidf_(b1z + red2(c1) + red2(c4));
        float n1  = tanhf_(b1xn + red2(c2) + r1 * (b1hn + red2(c5)));
        float h1n = fmaf(z1, h1[d] - n1, n1);
        __syncthreads();
        h1[d] = h1n;
        acc += h1n;
        g_u0[s * DD + d] = h0n;
        g_u1[s * DD + d] = h1n;
        g_ua[s * DD + d] = acc;
        __syncthreads();
    }
}

// ---------------- one layer, one timestep, N active slots ----------------
template<int N>
__device__ __forceinline__ void layer_pass(
    const float4* __restrict__ wmat,
    const float* __restrict__ opsrc,           // [TG][DD] (slot-indexed)
    float* __restrict__ hstate,                // [TG][DD]
    float* __restrict__ ph,                    // [TG][3][DD]
    float* __restrict__ accs,                  // [TG][DD] or nullptr
    float br, float bz, float bn,
    int side, int d)
{
    u64 a0[N], a1[N], a2[N];
    {
        const u64 vr = set_lo(br), vz = set_lo(bz), vn = set_lo(bn);
#pragma unroll
        for (int g = 0; g < N; ++g) { a0[g] = vr; a1[g] = vz; a2[g] = vn; }
    }
    const char* wp = (const char*)(wmat + d);
    const char* op = (const char*)opsrc;
#pragma unroll 1
    for (int kb = 0; kb < 64; ++kb) {
        ulonglong2 wr = *(const ulonglong2*)(wp);
        ulonglong2 wz = *(const ulonglong2*)(wp + DD * 16);
        ulonglong2 wn = *(const ulonglong2*)(wp + 2 * DD * 16);
#pragma unroll
        for (int g = 0; g < N; ++g) {
            ulonglong2 ov = *(const ulonglong2*)(op + g * (DD * 4));
            a0[g] = fma2(wr.x, ov.x, a0[g]);
            a0[g] = fma2(wr.y, ov.y, a0[g]);
            a1[g] = fma2(wz.x, ov.x, a1[g]);
            a1[g] = fma2(wz.y, ov.y, a1[g]);
            a2[g] = fma2(wn.x, ov.x, a2[g]);
            a2[g] = fma2(wn.y, ov.y, a2[g]);
        }
        wp += GD * 16;
        op += 16;
    }

    if (side) {
#pragma unroll
        for (int g = 0; g < N; ++g) {
            float* p = ph + g * (3 * DD);
            p[d]          = red2(a0[g]);
            p[DD + d]     = red2(a1[g]);
            p[2 * DD + d] = red2(a2[g]);
        }
        __syncthreads();   // partials visible
        __syncthreads();   // wait for ih h-update
    } else {
        __syncthreads();   // wait for hh partials
#pragma unroll
        for (int g = 0; g < N; ++g) {
            const float* p = ph + g * (3 * DD);
            float r  = sigmoidf_(red2(a0[g]) + p[d]);
            float z  = sigmoidf_(red2(a1[g]) + p[DD + d]);
            float n  = tanhf_(fmaf(r, p[2 * DD + d], red2(a2[g])));
            float h  = hstate[g * DD + d];
            float hnew = fmaf(z, h - n, n);
            hstate[g * DD + d] = hnew;
            if (accs) accs[g * DD + d] += hnew;
        }
        __syncthreads();   // new h visible to hh side
    }
}

// ---------------- main persistent kernel ----------------
__global__ __launch_bounds__(NT, 1) void gru_main(
    const float* __restrict__ x,
    const float* __restrict__ bih0, const float* __restrict__ bhh0,
    const float* __restrict__ bih1, const float* __restrict__ bhh1,
    float* __restrict__ out, int B)
{
    extern __shared__ float sm[];
    float* xs   = sm;                       // [TG][DD]
    float* h0s  = sm + 1 * TG * DD;         // [TG][DD]
    float* h1s  = sm + 2 * TG * DD;         // [TG][DD]
    float* accs = sm + 3 * TG * DD;         // [TG][DD]
    float* ph   = sm + 4 * TG * DD;         // [TG][3][DD]
    int*   ord  = (int*)(sm + 7 * TG * DD); // [TG][LL]

    __shared__ int cs_raw[TG], p_sm[TG], sc_sm[TG], st_sm[TG], tI_sm[TG];
    __shared__ unsigned char Nt_sm[LL];

    const int tid  = threadIdx.x;
    const int side = tid >> 8;          // 0 = ih warpgroup, 1 = hh warpgroup
    const int d    = tid & (DD - 1);
    const int g0   = blockIdx.x * TG;

    // ---- schedule: sort groups by count desc, compute N(t) and inclusion times ----
    if (tid < TG) {
        const int grp = g0 + tid;
        cs_raw[tid] = (grp < B) ? g_cnt[grp] : 0;
    }
    __syncthreads();
    if (tid < TG) {
        const int c = cs_raw[tid];
        int rank = 0;
        for (int j = 0; j < TG; ++j) {
            const int cj = cs_raw[j];
            rank += (cj > c || (cj == c && j < tid)) ? 1 : 0;
        }
        p_sm[rank]  = tid;
        sc_sm[rank] = c;
    }
    __syncthreads();
    if (tid < TG) st_sm[tid] = LL - sc_sm[tid];   // start times, ascending
    __syncthreads();
    if (tid < LL) {
        int A = 0;
        for (int g = 0; g < TG; ++g) A += (st_sm[g] <= tid) ? 1 : 0;
        Nt_sm[tid] = (A <= 4) ? 4 : (A <= 8) ? 8 : (A <= 11) ? 11 : 14;
    }
    __syncthreads();
    if (tid < TG) {
        int tI = 0;
        while (tI < LL && (int)Nt_sm[tI] <= tid) ++tI;
        tI_sm[tid] = tI;                 // first step this slot is computed
    }
    __syncthreads();

    // ---- init states from universal pad trajectory at inclusion time ----
    for (int i = tid; i < TG * DD; i += NT) {
        const int slot = i >> 8;
        const int dd   = i & (DD - 1);
        const int tI   = tI_sm[slot];
        h0s[i]  = g_u0[tI * DD + dd];
        h1s[i]  = g_u1[tI * DD + dd];
        accs[i] = g_ua[tI * DD + dd];
    }
    // stage group order (slot-indexed)
    for (int k = tid; k < TG * LL; k += NT) {
        const int slot = k / LL;
        const int grp  = g0 + p_sm[slot];
        ord[k] = (grp < B) ? g_order[grp * LL + (k - slot * LL)] : -1;
    }
    __syncthreads();

    const float* bv0 = side ? bhh0 : bih0;
    const float* bv1 = side ? bhh1 : bih1;
    const float b0r = bv0[d], b0z = bv0[DD + d], b0n = bv0[2 * DD + d];
    const float b1r = bv1[d], b1z = bv1[DD + d], b1n = bv1[2 * DD + d];
    const float4* w0 = g_wpack + (size_t)(side ? 1 : 0) * 64 * GD;
    const float4* w1 = g_wpack + (size_t)(side ? 3 : 2) * 64 * GD;

#pragma unroll 1
    for (int t = 0; t < LL; ++t) {
        const int nb = Nt_sm[t];
        // gather x_t for active slots (inactive ones: ord = -1 -> 0)
        for (int k = tid; k < nb * DD; k += NT) {
            const int slot = k >> 8;
            const int dd   = k & (DD - 1);
            const int e    = ord[slot * LL + t];
            xs[k] = (e >= 0) ? x[(size_t)e * DD + dd] : 0.f;
        }
        __syncthreads();

        if (nb == 4) {
            layer_pass<4>(w0, side ? h0s : xs,  h0s, ph, nullptr, b0r, b0z, b0n, side, d);
            layer_pass<4>(w1, side ? h1s : h0s, h1s, ph, accs,    b1r, b1z, b1n, side, d);
        } else if (nb == 8) {
            layer_pass<8>(w0, side ? h0s : xs,  h0s, ph, nullptr, b0r, b0z, b0n, side, d);
            layer_pass<8>(w1, side ? h1s : h0s, h1s, ph, accs,    b1r, b1z, b1n, side, d);
        } else if (nb == 11) {
            layer_pass<11>(w0, side ? h0s : xs,  h0s, ph, nullptr, b0r, b0z, b0n, side, d);
            layer_pass<11>(w1, side ? h1s : h0s, h1s, ph, accs,    b1r, b1z, b1n, side, d);
        } else {
            layer_pass<14>(w0, side ? h0s : xs,  h0s, ph, nullptr, b0r, b0z, b0n, side, d);
            layer_pass<14>(w1, side ? h1s : h0s, h1s, ph, accs,    b1r, b1z, b1n, side, d);
        }
    }

    if (side == 0) {
#pragma unroll
        for (int slot = 0; slot < TG; ++slot) {
            const int grp = g0 + p_sm[slot];
            if (grp < B) out[(size_t)grp * DD + d] = accs[slot * DD + d] * (1.0f / LL);
        }
    }
}

// ---------------- entry point ----------------
extern "C" void kernel_launch(void* const* d_in, const int* in_sizes, int n_in,
                              void* d_out, int out_size) {
    const float* x     = (const float*)d_in[0];
    const float* ts    = (const float*)d_in[1];
    const float* wih0  = (const float*)d_in[2];
    const float* whh0  = (const float*)d_in[3];
    const float* bih0  = (const float*)d_in[4];
    const float* bhh0  = (const float*)d_in[5];
    const float* wih1  = (const float*)d_in[6];
    const float* whh1  = (const float*)d_in[7];
    const float* bih1  = (const float*)d_in[8];
    const float* bhh1  = (const float*)d_in[9];
    const int*   index = (const int*)d_in[10];
    float* out = (float*)d_out;

    const int E = in_sizes[0] / DD;
    const int B = out_size / DD;

    const int smem = (7 * TG * DD) * (int)sizeof(float) + (TG * LL) * (int)sizeof(int);
    cudaFuncSetAttribute(gru_main, cudaFuncAttributeMaxDynamicSharedMemorySize, smem);

    setup_k<<<B + 768, 256>>>(ts, index, E, B, wih0, whh0, wih1, whh1);
    pad_k<<<1, 256>>>(wih1, whh0, whh1, bih0, bhh0, bih1, bhh1);

    const int nb = (B + TG - 1) / TG;   // 147 blocks for B=2048 -> one wave on 148 SMs
    gru_main<<<nb, NT, smem>>>(x, bih0, bhh0, bih1, bhh1, out, B);
}

// round 7
// speedup vs baseline: 1.7836x; 1.7836x over previous
#include <cuda_runtime.h>
#include <cstdint>

#define DD 256      // feature/hidden dim
#define GD 768      // 3*DD gate dim
#define LL 96       // max group length
#define TG 14       // groups per block
#define BMAX 2048
#define NT 512      // threads per block (2 warpgroups: ih / hh)

typedef unsigned long long u64;

// ---------------- device scratch ----------------
__device__ int    g_order[BMAX * LL];          // edge id per (group, t), -1 = pad
__device__ float4 g_wpack[4 * 64 * GD];        // [mat][kb][gd] -> W[gd][4kb..4kb+3]

// ---------------- helpers ----------------
__device__ __forceinline__ u64 fma2(u64 a, u64 b, u64 c) {
    u64 d;
    asm("fma.rn.f32x2 %0, %1, %2, %3;" : "=l"(d) : "l"(a), "l"(b), "l"(c));
    return d;
}
__device__ __forceinline__ float red2(u64 a) {
    float lo = __uint_as_float((unsigned)(a & 0xffffffffULL));
    float hi = __uint_as_float((unsigned)(a >> 32));
    return lo + hi;
}
__device__ __forceinline__ u64 set_lo(float v) { return (u64)__float_as_uint(v); }

__device__ __forceinline__ float sigmoidf_(float v) {
    return __fdividef(1.f, 1.f + __expf(-v));
}
__device__ __forceinline__ float tanhf_(float v) {
    float t = __expf(2.f * v);
    return 1.f - __fdividef(2.f, t + 1.f);
}

__device__ __forceinline__ void cpa16(uint32_t dst, const void* src) {
    asm volatile("cp.async.cg.shared.global [%0], [%1], 16;\n" :: "r"(dst), "l"(src));
}
#define CPA_COMMIT() asm volatile("cp.async.commit_group;\n" ::)
#define CPA_WAIT1()  asm volatile("cp.async.wait_group 1;\n" ::: "memory")

// ---------------- fused setup: per-group timestamp sort + weight pack ----------------
__global__ void setup_k(const float* __restrict__ ts, const int* __restrict__ index,
                        int E, int B,
                        const float* __restrict__ w0, const float* __restrict__ w1,
                        const float* __restrict__ w2, const float* __restrict__ w3)
{
    const int b = blockIdx.x;
    if (b < B) {
        __shared__ int   lbub[2];
        __shared__ float sts[LL];
        const int i = threadIdx.x;
        if (i < 2) {
            const int key = b + i;
            int lo = 0, hi = E;
            while (lo < hi) {
                int m = (lo + hi) >> 1;
                if (index[m] < key) lo = m + 1; else hi = m;
            }
            lbub[i] = lo;
        }
        __syncthreads();
        const int off = lbub[0];
        const int c   = lbub[1] - lbub[0];
        if (i < c)  sts[i] = ts[off + i];
        if (i < LL) g_order[b * LL + i] = -1;
        __syncthreads();
        if (i < c) {
            const float ti = sts[i];
            int rank = 0;
            for (int j = 0; j < c; ++j) {
                float tj = sts[j];
                rank += (tj < ti || (tj == ti && j < i)) ? 1 : 0;
            }
            g_order[b * LL + (LL - c + rank)] = off + i;
        }
    } else {
        int idx = (b - B) * 256 + threadIdx.x;
        if (idx < 4 * 64 * GD) {
            int m   = idx / (64 * GD);
            int rem = idx - m * 64 * GD;
            int kb  = rem / GD;
            int dd  = rem - kb * GD;
            const float* W = (m == 0) ? w0 : (m == 1) ? w1 : (m == 2) ? w2 : w3;
            const float* p = W + dd * DD + kb * 4;
            g_wpack[idx] = make_float4(p[0], p[1], p[2], p[3]);
        }
    }
}

// ---------------- one layer, one timestep ----------------
// side 0 (threads 0-255): W_ih rows vs `opsrc` (layer input); combines with hh
//   partials, applies activations, updates hstate (+ pooled accs).
// side 1 (threads 256-511): W_hh rows vs hstate (old h); publishes partials.
// Weights stream global->smem via per-thread cp.async, depth-2 double buffer.
__device__ __forceinline__ void layer_pass(
    const float4* __restrict__ wmat,           // this side's packed matrix
    const float4* __restrict__ wsm,            // this thread's smem weight slot (gate r)
    uint32_t wsm_u32,                          // same, as shared-space address
    const float* __restrict__ opsrc,           // [TG][DD]
    float* __restrict__ hstate,                // [TG][DD]
    float* __restrict__ ph,                    // [TG][3][DD]
    float* __restrict__ accs,                  // [TG][DD] or nullptr
    float br, float bz, float bn,
    int side, int d)
{
    u64 a0[TG], a1[TG], a2[TG];
    {
        const u64 vr = set_lo(br), vz = set_lo(bz), vn = set_lo(bn);
#pragma unroll
        for (int g = 0; g < TG; ++g) { a0[g] = vr; a1[g] = vz; a2[g] = vn; }
    }

    const char* wg = (const char*)(wmat + d);         // gate r row, +GD*16 per kb

    // prologue: kb 0 -> stage 0
    cpa16(wsm_u32,               wg);
    cpa16(wsm_u32 + DD * 16,     wg + DD * 16);
    cpa16(wsm_u32 + 2 * DD * 16, wg + 2 * DD * 16);
    CPA_COMMIT();

    const char* op = (const char*)opsrc;

#pragma unroll 1
    for (int kb = 0; kb < 64; ++kb) {
        // issue kb+1 into the other stage (wraps to kb0 at the end; harmless)
        {
            const int   kn   = (kb + 1) & 63;
            const char* wnn  = (const char*)(wmat + (size_t)kn * GD + d);
            const uint32_t s = wsm_u32 + ((kb + 1) & 1) * (6 * DD * 16);
            cpa16(s,               wnn);
            cpa16(s + DD * 16,     wnn + DD * 16);
            cpa16(s + 2 * DD * 16, wnn + 2 * DD * 16);
            CPA_COMMIT();
        }
        CPA_WAIT1();   // current stage (committed last iter / prologue) has landed

        const float4* wc = wsm + (kb & 1) * (6 * DD);
        ulonglong2 wr = *(const ulonglong2*)(wc);
        ulonglong2 wz = *(const ulonglong2*)(wc + DD);
        ulonglong2 wn = *(const ulonglong2*)(wc + 2 * DD);
#pragma unroll
        for (int g = 0; g < TG; ++g) {
            ulonglong2 ov = *(const ulonglong2*)(op + g * (DD * 4));
            a0[g] = fma2(wr.x, ov.x, a0[g]);
            a0[g] = fma2(wr.y, ov.y, a0[g]);
            a1[g] = fma2(wz.x, ov.x, a1[g]);
            a1[g] = fma2(wz.y, ov.y, a1[g]);
            a2[g] = fma2(wn.x, ov.x, a2[g]);
            a2[g] = fma2(wn.y, ov.y, a2[g]);
        }
        op += 16;
    }

    if (side) {
        // hh: publish partials
#pragma unroll
        for (int g = 0; g < TG; ++g) {
            float* p = ph + g * (3 * DD);
            p[d]          = red2(a0[g]);
            p[DD + d]     = red2(a1[g]);
            p[2 * DD + d] = red2(a2[g]);
        }
        __syncthreads();   // partials visible
        __syncthreads();   // wait for ih h-update
    } else {
        __syncthreads();   // wait for hh partials
#pragma unroll
        for (int g = 0; g < TG; ++g) {
            const float* p = ph + g * (3 * DD);
            float r  = sigmoidf_(red2(a0[g]) + p[d]);
            float z  = sigmoidf_(red2(a1[g]) + p[DD + d]);
            float n  = tanhf_(fmaf(r, p[2 * DD + d], red2(a2[g])));
            float h  = hstate[g * DD + d];
            float hnew = fmaf(z, h - n, n);            // (1-z)n + z h
            hstate[g * DD + d] = hnew;
            if (accs) accs[g * DD + d] += hnew;
        }
        __syncthreads();   // new h visible to hh side
    }
}

// ---------------- main persistent kernel ----------------
__global__ __launch_bounds__(NT, 1) void gru_main(
    const float* __restrict__ x,
    const float* __restrict__ bih0, const float* __restrict__ bhh0,
    const float* __restrict__ bih1, const float* __restrict__ bhh1,
    float* __restrict__ out, int B)
{
    extern __shared__ float sm[];
    float*  xs   = sm;                      // [TG][DD]
    float*  h0s  = sm + 1 * TG * DD;        // [TG][DD]
    float*  h1s  = sm + 2 * TG * DD;        // [TG][DD]
    float*  accs = sm + 3 * TG * DD;        // [TG][DD]
    float*  ph   = sm + 4 * TG * DD;        // [TG][3][DD]
    float4* wbuf = (float4*)(sm + 7 * TG * DD);  // [2 stages][2 sides][3 gates][DD]

    const int tid  = threadIdx.x;
    const int side = tid >> 8;          // 0 = ih warpgroup, 1 = hh warpgroup
    const int d    = tid & (DD - 1);
    const int g0   = blockIdx.x * TG;

    // this thread's smem weight slot (stage 0, its side, gate r, its d)
    float4*  wsm     = wbuf + side * (3 * DD) + d;
    uint32_t wsm_u32 = (uint32_t)__cvta_generic_to_shared(wsm);

    const float* bv0 = side ? bhh0 : bih0;
    const float* bv1 = side ? bhh1 : bih1;
    const float b0r = bv0[d], b0z = bv0[DD + d], b0n = bv0[2 * DD + d];
    const float b1r = bv1[d], b1z = bv1[DD + d], b1n = bv1[2 * DD + d];
    const float4* w0 = g_wpack + (size_t)(side ? 1 : 0) * 64 * GD;
    const float4* w1 = g_wpack + (size_t)(side ? 3 : 2) * 64 * GD;

    // zero h0s, h1s, accs (contiguous)
    for (int i = tid; i < 3 * TG * DD; i += NT) h0s[i] = 0.f;
    __syncthreads();

#pragma unroll 1
    for (int t = 0; t < LL; ++t) {
        // gather x_t for all groups (zeros for pads / out-of-range groups)
        for (int k = tid; k < TG * DD; k += NT) {
            const int g   = k >> 8;
            const int dd  = k & (DD - 1);
            const int grp = g0 + g;
            int e = (grp < B) ? g_order[grp * LL + t] : -1;
            xs[k] = (e >= 0) ? x[(size_t)e * DD + dd] : 0.f;
        }
        __syncthreads();

        // layer 0: ih streams xs, hh streams h0s; ih updates h0s
        layer_pass(w0, wsm, wsm_u32, side ? h0s : xs, h0s, ph, nullptr,
                   b0r, b0z, b0n, side, d);
        // layer 1: ih streams new h0s, hh streams h1s; ih updates h1s + pool
        layer_pass(w1, wsm, wsm_u32, side ? h1s : h0s, h1s, ph, accs,
                   b1r, b1z, b1n, side, d);
    }

    if (side == 0) {
#pragma unroll
        for (int g = 0; g < TG; ++g) {
            const int grp = g0 + g;
            if (grp < B) out[(size_t)grp * DD + d] = accs[g * DD + d] * (1.0f / LL);
        }
    }
}

// ---------------- entry point ----------------
extern "C" void kernel_launch(void* const* d_in, const int* in_sizes, int n_in,
                              void* d_out, int out_size) {
    const float* x     = (const float*)d_in[0];
    const float* ts    = (const float*)d_in[1];
    const float* wih0  = (const float*)d_in[2];
    const float* whh0  = (const float*)d_in[3];
    const float* bih0  = (const float*)d_in[4];
    const float* bhh0  = (const float*)d_in[5];
    const float* wih1  = (const float*)d_in[6];
    const float* whh1  = (const float*)d_in[7];
    const float* bih1  = (const float*)d_in[8];
    const float* bhh1  = (const float*)d_in[9];
    const int*   index = (const int*)d_in[10];
    float* out = (float*)d_out;

    const int E = in_sizes[0] / DD;
    const int B = out_size / DD;

    // smem: 7*TG*DD floats state + 2*2*3*DD float4 weight stages
    const int smem = (7 * TG * DD) * (int)sizeof(float) + 12 * DD * (int)sizeof(float4);
    cudaFuncSetAttribute(gru_main, cudaFuncAttributeMaxDynamicSharedMemorySize, smem);

    setup_k<<<B + 768, 256>>>(ts, index, E, B, wih0, whh0, wih1, whh1);

    int nb = (B + TG - 1) / TG;
    if (nb < 148) nb = 148;             // avoid sub-148-grid issue throttle
    gru_main<<<nb, NT, smem>>>(x, bih0, bhh0, bih1, bhh1, out, B);
}